// round 2
// baseline (speedup 1.0000x reference)
#include <cuda_runtime.h>
#include <math_constants.h>

#define Ln  128
#define Bb  8
#define Dd  256
#define Hh  256
#define NHo 8
#define NGg 50

#define TJ    8
#define ROWS  64          // TJ * Bb rows per CTA
#define HSTR  260         // padded row stride for h1sm (260%32=4 -> conflict-free phase3)
#define SMEM_FLOATS (ROWS*HSTR + 64*256)

// Scratch (allocation-free rule: __device__ globals)
__device__ float g_A[Ln*Bb*Hh];    // x @ W1   indexed [j*B+b][h]
__device__ float g_Bv[Ln*Bb*Hh];   // x @ W2   indexed [i*B+b][h]
__device__ float g_WG[NGg*Hh];     // W_rbf @ W3
__device__ float g_cvec[Hh];       // b_in + b_rbf @ W3

__device__ __forceinline__ float gelu_f(float x) {
    // jax.nn.gelu approximate=True: 0.5x(1+tanh(sqrt(2/pi)(x+0.044715x^3)))
    float u = 0.7978845608028654f * fmaf(0.044715f * x, x * x, x);
    float a = fabsf(u);
    float e = __expf(-2.0f * a);
    float th = __fdividef(1.0f - e, 1.0f + e);
    th = (u >= 0.0f) ? th : -th;
    return 0.5f * x * (1.0f + th);
}

// ---------------------------------------------------------------------------
// Prep: A = x@W1, Bv = x@W2, WG = W_rbf@W3, cvec = b_in + b_rbf@W3
// One CTA per output row; 256 threads = one output column each.
// ---------------------------------------------------------------------------
__global__ void __launch_bounds__(256) prep_kernel(
    const float* __restrict__ x,     const float* __restrict__ W_rbf,
    const float* __restrict__ b_rbf, const float* __restrict__ W1,
    const float* __restrict__ W2,    const float* __restrict__ W3,
    const float* __restrict__ b_in)
{
    __shared__ float vsm[Dd];
    const int row = blockIdx.x;
    const int h   = threadIdx.x;

    const float* vec; const float* Wm; float* outp; bool add_bin = false;
    if (row < Ln*Bb)            { vec = x + row*Dd;             Wm = W1; outp = g_A  + row*Hh; }
    else if (row < 2*Ln*Bb)     { vec = x + (row - Ln*Bb)*Dd;   Wm = W2; outp = g_Bv + (row - Ln*Bb)*Hh; }
    else if (row < 2*Ln*Bb+NGg) { vec = W_rbf + (row - 2*Ln*Bb)*Dd; Wm = W3; outp = g_WG + (row - 2*Ln*Bb)*Hh; }
    else                        { vec = b_rbf; Wm = W3; outp = g_cvec; add_bin = true; }

    vsm[h] = vec[h];
    __syncthreads();

    float acc = 0.0f;
    #pragma unroll 8
    for (int d = 0; d < Dd; d++)
        acc = fmaf(vsm[d], Wm[d*Hh + h], acc);
    if (add_bin) acc += b_in[h];
    outp[h] = acc;
}

// ---------------------------------------------------------------------------
// Main fused kernel. CTA = (i, 8 consecutive j) -> 64 rows (j_local*8 + b).
// Phase 1: pre = A[j,b] + Bv[i,b] + gauss @ WG + cvec ; h1 = gelu(pre)
// Phase 2: t = h1 @ W_res ; h2 = h1 + gelu(t + b_res)
// Phase 3: out = h2 @ W_out + b_out, masked, transposed write.
// ---------------------------------------------------------------------------
__global__ void __launch_bounds__(256, 1) pair_kernel(
    const float* __restrict__ dist, const int* __restrict__ mask,
    const float* __restrict__ W_res, const float* __restrict__ b_res,
    const float* __restrict__ W_out, const float* __restrict__ b_out,
    float* __restrict__ out)
{
    extern __shared__ float smem[];
    float* h1sm = smem;                  // [ROWS][HSTR]
    float* buf  = smem + ROWS*HSTR;      // 16384 floats, multi-purpose
    __shared__ float dsm[ROWS];

    const int i    = blockIdx.y;
    const int j0   = blockIdx.x * TJ;
    const int t    = threadIdx.x;
    const int w    = t >> 5;
    const int lane = t & 31;
    const int r0   = w * 8;              // this warp owns rows r0..r0+7

    // ---- stage dist (64 contiguous floats) and WG (50x256) ----
    float* gsm = buf;                    // [ROWS][52]
    float* WGs = buf + ROWS*52;          // [NG][256]  (3328 + 12800 <= 16384)
    if (t < ROWS) dsm[t] = dist[i*(Ln*Bb) + j0*Bb + t];
    for (int idx = t; idx < NGg*Hh; idx += 256) WGs[idx] = g_WG[idx];
    __syncthreads();

    // ---- gaussian smearing ----
    const float delta = 12.0f / 49.0f;
    const float coeff = -0.5f / (delta * delta);
    for (int e = t; e < ROWS*NGg; e += 256) {
        int r = e / NGg, g = e - r * NGg;
        float dv = dsm[r] - delta * (float)g;
        gsm[r*52 + g] = __expf(coeff * dv * dv);
    }
    __syncthreads();

    // ---- phase 1 GEMM: [64 x 50] @ [50 x 256], 8x8 register blocking ----
    float acc[8][8];
    #pragma unroll
    for (int rr = 0; rr < 8; rr++)
        #pragma unroll
        for (int cc = 0; cc < 8; cc++) acc[rr][cc] = 0.0f;

    #pragma unroll 2
    for (int g = 0; g < NGg; g++) {
        float wv[8], gv[8];
        #pragma unroll
        for (int cc = 0; cc < 8; cc++) wv[cc] = WGs[g*Hh + lane + 32*cc];
        #pragma unroll
        for (int rr = 0; rr < 8; rr++) gv[rr] = gsm[(r0+rr)*52 + g];
        #pragma unroll
        for (int rr = 0; rr < 8; rr++)
            #pragma unroll
            for (int cc = 0; cc < 8; cc++)
                acc[rr][cc] = fmaf(gv[rr], wv[cc], acc[rr][cc]);
    }

    // ---- epilogue 1: add A/Bv/cvec, gelu, store h1 ----
    #pragma unroll
    for (int rr = 0; rr < 8; rr++) {
        const int row = r0 + rr;
        const int b   = row & 7;
        const float* Ap = g_A  + (j0*Bb + row)*Hh;
        const float* Bp = g_Bv + (i*Bb  + b  )*Hh;
        #pragma unroll
        for (int cc = 0; cc < 8; cc++) {
            int hcol = lane + 32*cc;
            float v = acc[rr][cc] + Ap[hcol] + Bp[hcol] + g_cvec[hcol];
            h1sm[row*HSTR + hcol] = gelu_f(v);
        }
    }
    __syncthreads();

    // ---- phase 2 GEMM: [64 x 256] @ [256 x 256], K staged in 4 chunks ----
    float acc2[8][8];
    #pragma unroll
    for (int rr = 0; rr < 8; rr++)
        #pragma unroll
        for (int cc = 0; cc < 8; cc++) acc2[rr][cc] = 0.0f;

    for (int kt = 0; kt < 4; kt++) {
        const float4* src = (const float4*)(W_res + kt*64*Hh);
        float4* dst = (float4*)buf;
        #pragma unroll
        for (int idx = 0; idx < 16; idx++) dst[t + idx*256] = src[t + idx*256];
        __syncthreads();

        const int kbase = kt * 64;
        for (int hh = 0; hh < 64; hh++) {
            float hv[8], wv[8];
            #pragma unroll
            for (int rr = 0; rr < 8; rr++) hv[rr] = h1sm[(r0+rr)*HSTR + kbase + hh];
            #pragma unroll
            for (int cc = 0; cc < 8; cc++) wv[cc] = buf[hh*Hh + lane + 32*cc];
            #pragma unroll
            for (int rr = 0; rr < 8; rr++)
                #pragma unroll
                for (int cc = 0; cc < 8; cc++)
                    acc2[rr][cc] = fmaf(hv[rr], wv[cc], acc2[rr][cc]);
        }
        __syncthreads();
    }

    // ---- epilogue 2: h2 = h1 + gelu(t + b_res), write back in place ----
    #pragma unroll
    for (int rr = 0; rr < 8; rr++) {
        const int row = r0 + rr;
        #pragma unroll
        for (int cc = 0; cc < 8; cc++) {
            int k = lane + 32*cc;
            float tv = acc2[rr][cc] + b_res[k];
            h1sm[row*HSTR + k] = h1sm[row*HSTR + k] + gelu_f(tv);
        }
    }
    // stage W_out (256x8) into buf
    for (int idx = t; idx < Hh*NHo; idx += 256) buf[idx] = W_out[idx];
    __syncthreads();

    // ---- phase 3: out = h2 @ W_out + b_out, mask, transposed store ----
    const int row3 = t >> 2;            // 0..63
    const int o0   = (t & 3) * 2;       // 0,2,4,6
    float s0 = 0.0f, s1 = 0.0f;
    #pragma unroll 8
    for (int k = 0; k < Hh; k++) {
        float  hv = h1sm[row3*HSTR + k];
        float2 wv = *(const float2*)(buf + k*NHo + o0);
        s0 = fmaf(hv, wv.x, s0);
        s1 = fmaf(hv, wv.y, s1);
    }
    s0 += b_out[o0];
    s1 += b_out[o0 + 1];

    const int jl = row3 >> 3, b = row3 & 7;
    const int j  = j0 + jl;
    bool m = (mask[b*Ln + i] != 0) && (mask[b*Ln + j] != 0);
    if (!m) { s0 = -CUDART_INF_F; s1 = -CUDART_INF_F; }

    size_t obase = ((size_t)(b*NHo + o0))*(Ln*Ln) + (size_t)i*Ln + j;
    out[obase]         = s0;
    out[obase + Ln*Ln] = s1;
}

// ---------------------------------------------------------------------------
extern "C" void kernel_launch(void* const* d_in, const int* in_sizes, int n_in,
                              void* d_out, int out_size) {
    const float* x     = (const float*)d_in[0];
    const float* dist  = (const float*)d_in[1];
    const int*   mask  = (const int*)d_in[2];      // jax bool -> int32 in harness
    const float* W_rbf = (const float*)d_in[3];
    const float* b_rbf = (const float*)d_in[4];
    const float* W1    = (const float*)d_in[5];
    const float* W2    = (const float*)d_in[6];
    const float* W3    = (const float*)d_in[7];
    const float* b_in  = (const float*)d_in[8];
    const float* W_res = (const float*)d_in[9];
    const float* b_res = (const float*)d_in[10];
    const float* W_out = (const float*)d_in[11];
    const float* b_out = (const float*)d_in[12];
    float*       out   = (float*)d_out;

    prep_kernel<<<2*Ln*Bb + NGg + 1, 256>>>(x, W_rbf, b_rbf, W1, W2, W3, b_in);

    cudaFuncSetAttribute(pair_kernel, cudaFuncAttributeMaxDynamicSharedMemorySize,
                         SMEM_FLOATS * (int)sizeof(float));
    dim3 grid(Ln / TJ, Ln);
    pair_kernel<<<grid, 256, SMEM_FLOATS * sizeof(float)>>>(
        dist, mask, W_res, b_res, W_out, b_out, out);
}

// round 5
// speedup vs baseline: 4.0278x; 4.0278x over previous
#include <cuda_runtime.h>
#include <cuda_fp16.h>
#include <math_constants.h>
#include <cstdint>

#define Ln  128
#define Bb  8
#define Dd  256
#define Hh  256
#define NHo 8
#define NGg 50
#define TJ  16
#define ROWS 128

// strides
#define H1_STRB  528      // h1 fp16 row stride bytes (264 halves)
#define WT_STRB  528      // WresT fp16 row stride bytes
#define GA_STRB  144      // gauss fp16 row stride bytes (72 halves)
#define ACC_STRF 264      // acc fp32 scratch row stride (floats)

// smem byte offsets
#define SM_H1    0                      // 128*528 = 67584
#define SM_WT    67584                  // 256*528 = 135168 (aliases GA/WGT/ACC)
#define SM_GA    (SM_WT)                // 128*144 = 18432
#define SM_WGT   (SM_WT + 18432)        // 256*144 = 36864
#define SM_ACC   (SM_WT)                // 128*264*4 = 135168
#define SM_WOUT  202752                 // 256*8*4 = 8192
#define SM_CVEC  210944                 // 1024
#define SM_BRES  211968                 // 1024
#define SM_DSM   212992                 // 512
#define SM_RED   213504                 // 128*8*4 = 4096
#define SM_TOTAL 217600

// prep row decode boundaries (Ln*Bb = 1024 rows each for A and Bv)
#define PR_A    (Ln*Bb)                 // 1024
#define PR_BV   (2*Ln*Bb)               // 2048
#define PR_WGT  (2*Ln*Bb + NGg)         // 2098
#define PR_CV   (2*Ln*Bb + NGg + 1)     // 2099
#define PR_TOT  (PR_CV + Hh)            // 2355

// ---- device scratch (no allocs allowed) ----
__device__ float  g_A[Ln*Bb*Hh];      // x @ W1, row j*8+b
__device__ float  g_Bv[Ln*Bb*Hh];     // x @ W2, row i*8+b
__device__ float  g_cvec[Hh];         // b_in + b_rbf @ W3
__device__ __half g_WGT[Hh*64];       // [h][g] = (W_rbf@W3)[g][h], g>=50 zero
__device__ __half g_WresT[Hh*Hh];     // [n][k] = W_res[k][n]

__device__ __forceinline__ float gelu_f(float x) {
    float u = 0.7978845608028654f * fmaf(0.044715f * x, x * x, x);
    float t;
    asm("tanh.approx.f32 %0, %1;" : "=f"(t) : "f"(u));
    return 0.5f * x * (1.0f + t);
}

__device__ __forceinline__ void mma16816(float* c, const uint32_t* a, const uint32_t* b) {
    asm volatile(
        "mma.sync.aligned.m16n8k16.row.col.f32.f16.f16.f32 "
        "{%0,%1,%2,%3}, {%4,%5,%6,%7}, {%8,%9}, {%0,%1,%2,%3};"
        : "+f"(c[0]), "+f"(c[1]), "+f"(c[2]), "+f"(c[3])
        : "r"(a[0]), "r"(a[1]), "r"(a[2]), "r"(a[3]), "r"(b[0]), "r"(b[1]));
}

// Warp GEMM block: acc[4][8] m16n8k16 frags; A row-major [m][k] fp16, B [n][k] fp16.
template<int KS>
__device__ __forceinline__ void mma_block(
    const uint8_t* Abase, int astr_b, const uint8_t* Bbase, int bstr_b,
    int mrow0, int ncol0, int g, int tg, float acc[4][8][4])
{
    #pragma unroll
    for (int ks = 0; ks < KS; ks++) {
        const int k0 = ks * 16;
        uint32_t bf[8][2];
        #pragma unroll
        for (int nt = 0; nt < 8; nt++) {
            const uint8_t* bp = Bbase + (ncol0 + nt*8 + g) * bstr_b + (k0 + tg*2) * 2;
            bf[nt][0] = *(const uint32_t*)bp;
            bf[nt][1] = *(const uint32_t*)(bp + 16);
        }
        uint32_t af[4][4];
        #pragma unroll
        for (int mt = 0; mt < 4; mt++) {
            const uint8_t* ap = Abase + (mrow0 + mt*16 + g) * astr_b + (k0 + tg*2) * 2;
            af[mt][0] = *(const uint32_t*)ap;
            af[mt][1] = *(const uint32_t*)(ap + 8*astr_b);
            af[mt][2] = *(const uint32_t*)(ap + 16);
            af[mt][3] = *(const uint32_t*)(ap + 8*astr_b + 16);
        }
        #pragma unroll
        for (int mt = 0; mt < 4; mt++)
            #pragma unroll
            for (int nt = 0; nt < 8; nt++)
                mma16816(acc[mt][nt], af[mt], bf[nt]);
    }
}

__device__ __forceinline__ void spill_acc(
    uint8_t* smem, int mrow0, int ncol0, int g, int tg, float acc[4][8][4])
{
    #pragma unroll
    for (int mt = 0; mt < 4; mt++) {
        #pragma unroll
        for (int nt = 0; nt < 8; nt++) {
            const int r = mrow0 + mt*16 + g;
            const int c = ncol0 + nt*8 + tg*2;
            *(float2*)(smem + SM_ACC + (size_t)(r*ACC_STRF + c)*4) =
                make_float2(acc[mt][nt][0], acc[mt][nt][1]);
            *(float2*)(smem + SM_ACC + (size_t)((r+8)*ACC_STRF + c)*4) =
                make_float2(acc[mt][nt][2], acc[mt][nt][3]);
        }
    }
}

// ======================= prep =======================
__global__ void __launch_bounds__(256) prep_kernel(
    const float* __restrict__ x,     const float* __restrict__ W_rbf,
    const float* __restrict__ b_rbf, const float* __restrict__ W1,
    const float* __restrict__ W2,    const float* __restrict__ W3,
    const float* __restrict__ b_in,  const float* __restrict__ W_res)
{
    const int row = blockIdx.x;
    const int h   = threadIdx.x;

    if (row >= PR_CV + 1) {            // W_res transpose -> fp16: WresT[n][k]
        // rows PR_CV+1 .. PR_CV+Hh would be off-by-one; handled below instead
    }
    if (row >= PR_CV && row > PR_CV - 1 && row != PR_CV) { /* unreachable */ }

    if (row >= PR_CV + 0 && row >= 2099 + 0 && row >= PR_TOT) return;

    if (row >= 2099) {                 // WresT rows: 2099 .. 2354
        int k = row - 2099;
        g_WresT[h*Hh + k] = __float2half(W_res[k*Hh + h]);
        return;
    }

    __shared__ float vsm[Dd];
    const float* vec; const float* Wm;
    if (row < PR_A)        { vec = x + row*Dd;            Wm = W1; }
    else if (row < PR_BV)  { vec = x + (row - PR_A)*Dd;   Wm = W2; }
    else if (row < PR_WGT) { vec = W_rbf + (row - PR_BV)*Dd; Wm = W3; }
    else                   { vec = b_rbf;                 Wm = W3; }

    vsm[h] = vec[h];
    __syncthreads();

    float acc = 0.0f;
    #pragma unroll 8
    for (int d = 0; d < Dd; d++)
        acc = fmaf(vsm[d], Wm[d*Hh + h], acc);

    if (row < PR_A)        g_A[row*Hh + h] = acc;
    else if (row < PR_BV)  g_Bv[(row - PR_A)*Hh + h] = acc;
    else if (row < PR_WGT) g_WGT[h*64 + (row - PR_BV)] = __float2half(acc);
    else {
        g_cvec[h] = acc + b_in[h];
        #pragma unroll
        for (int g = NGg; g < 64; g++) g_WGT[h*64 + g] = __float2half(0.0f);
    }
}

// ======================= main fused HMMA kernel =======================
__global__ void __launch_bounds__(256, 1) pair_kernel(
    const float* __restrict__ dist, const int* __restrict__ mask,
    const float* __restrict__ b_res, const float* __restrict__ W_out,
    const float* __restrict__ b_out, float* __restrict__ out)
{
    extern __shared__ __align__(16) uint8_t smem[];

    const int t    = threadIdx.x;
    const int wid  = t >> 5;
    const int lane = t & 31;
    const int g    = lane >> 2;
    const int tg   = lane & 3;
    const int i    = blockIdx.y;
    const int j0   = blockIdx.x * TJ;
    const int mrow0 = (wid & 1) * 64;
    const int ncol0 = (wid >> 1) * 64;

    float* cvec_s = (float*)(smem + SM_CVEC);
    float* bres_s = (float*)(smem + SM_BRES);
    float* wout_s = (float*)(smem + SM_WOUT);
    float* dsm    = (float*)(smem + SM_DSM);
    float* red    = (float*)(smem + SM_RED);

    // ---- stage small buffers + WGT ----
    cvec_s[t] = g_cvec[t];
    bres_s[t] = b_res[t];
    #pragma unroll
    for (int q = 0; q < 8; q++) wout_s[t + q*256] = W_out[t + q*256];
    if (t < ROWS) dsm[t] = dist[i*(Ln*Bb) + j0*Bb + t];
    {
        const uint4* wgt4 = (const uint4*)g_WGT;   // 256 rows x 8 uint4
        #pragma unroll
        for (int q = 0; q < 8; q++) {
            int u = t + q*256;
            int n = u >> 3, c = u & 7;
            *(uint4*)(smem + SM_WGT + n*GA_STRB + c*16) = wgt4[u];
        }
    }
    __syncthreads();

    // ---- gaussian smearing -> GA fp16 [128][64], zero-padded k>=50 ----
    {
        const float delta = 12.0f / 49.0f;
        const float coeff = -0.5f / (delta * delta);
        #pragma unroll
        for (int q = 0; q < 16; q++) {
            int p2 = t + 256*q;            // half2 index
            int r = p2 >> 5, kp = p2 & 31;
            int k = 2*kp;
            float d = dsm[r];
            float v0 = 0.0f, v1 = 0.0f;
            if (k < NGg)     { float d0 = d - delta*(float)k;     v0 = __expf(coeff*d0*d0); }
            if (k+1 < NGg)   { float d1 = d - delta*(float)(k+1); v1 = __expf(coeff*d1*d1); }
            *(__half2*)(smem + SM_GA + r*GA_STRB + k*2) = __floats2half2_rn(v0, v1);
        }
    }
    __syncthreads();

    float acc[4][8][4];
    #pragma unroll
    for (int mt = 0; mt < 4; mt++)
        #pragma unroll
        for (int nt = 0; nt < 8; nt++)
            #pragma unroll
            for (int e = 0; e < 4; e++) acc[mt][nt][e] = 0.0f;

    // ---- MMA1: D1 = gauss[128x64] @ WG[64x256] ----
    mma_block<4>(smem + SM_GA, GA_STRB, smem + SM_WGT, GA_STRB, mrow0, ncol0, g, tg, acc);
    __syncthreads();                       // all warps done reading GA/WGT
    spill_acc(smem, mrow0, ncol0, g, tg, acc);
    __syncthreads();

    // ---- epilogue 1 (row-linear): h1 = gelu(D1 + A + Bv + cvec) -> fp16 ----
    #pragma unroll
    for (int q = 0; q < 32; q++) {
        int e4 = t + 256*q;                // float4 index over [128][64]
        int row = e4 >> 6, c4 = e4 & 63;
        int col = c4 * 4;
        float4 a  = *(const float4*)(smem + SM_ACC + (size_t)(row*ACC_STRF + col)*4);
        float4 xa = *(const float4*)(g_A  + (size_t)(j0*Bb + row)*Hh + col);
        float4 xb = *(const float4*)(g_Bv + (size_t)(i*Bb + (row & 7))*Hh + col);
        float4 cv = *(const float4*)(cvec_s + col);
        float v0 = a.x + xa.x + xb.x + cv.x;
        float v1 = a.y + xa.y + xb.y + cv.y;
        float v2 = a.z + xa.z + xb.z + cv.z;
        float v3 = a.w + xa.w + xb.w + cv.w;
        *(__half2*)(smem + SM_H1 + row*H1_STRB + col*2)     = __floats2half2_rn(gelu_f(v0), gelu_f(v1));
        *(__half2*)(smem + SM_H1 + row*H1_STRB + col*2 + 4) = __floats2half2_rn(gelu_f(v2), gelu_f(v3));
    }
    __syncthreads();

    // ---- stage WresT [256][256] fp16 into WT ----
    {
        const uint4* ws4 = (const uint4*)g_WresT;  // 256 rows x 32 uint4
        #pragma unroll
        for (int q = 0; q < 32; q++) {
            int u = t + 256*q;
            int n = u >> 5, c = u & 31;
            *(uint4*)(smem + SM_WT + n*WT_STRB + c*16) = ws4[u];
        }
    }
    __syncthreads();

    // ---- MMA2: D2 = h1[128x256] @ W_res[256x256] ----
    #pragma unroll
    for (int mt = 0; mt < 4; mt++)
        #pragma unroll
        for (int nt = 0; nt < 8; nt++)
            #pragma unroll
            for (int e = 0; e < 4; e++) acc[mt][nt][e] = 0.0f;
    mma_block<16>(smem + SM_H1, H1_STRB, smem + SM_WT, WT_STRB, mrow0, ncol0, g, tg, acc);
    __syncthreads();                       // all warps done reading WT
    spill_acc(smem, mrow0, ncol0, g, tg, acc);
    __syncthreads();

    // ---- epilogue 2 (row-linear, in place): h2 = h1 + gelu(D2 + b_res) ----
    #pragma unroll
    for (int q = 0; q < 32; q++) {
        int e4 = t + 256*q;
        int row = e4 >> 6, c4 = e4 & 63;
        int col = c4 * 4;
        float* ap = (float*)(smem + SM_ACC + (size_t)(row*ACC_STRF + col)*4);
        float4 a  = *(const float4*)ap;
        float4 rb = *(const float4*)(bres_s + col);
        uint2 hh  = *(const uint2*)(smem + SM_H1 + row*H1_STRB + col*2);
        float2 f01 = __half22float2(*(__half2*)&hh.x);
        float2 f23 = __half22float2(*(__half2*)&hh.y);
        float4 o;
        o.x = f01.x + gelu_f(a.x + rb.x);
        o.y = f01.y + gelu_f(a.y + rb.y);
        o.z = f23.x + gelu_f(a.z + rb.z);
        o.w = f23.y + gelu_f(a.w + rb.w);
        *(float4*)ap = o;
    }
    __syncthreads();

    // ---- phase 3: out = h2 @ W_out + b_out ----
    const int row3 = t >> 1;
    const int half = t & 1;
    float s[8];
    #pragma unroll
    for (int o = 0; o < 8; o++) s[o] = 0.0f;
    const float* accrow = (const float*)(smem + SM_ACC) + (size_t)row3*ACC_STRF + half*128;
    #pragma unroll 4
    for (int c = 0; c < 128; c += 4) {
        float4 h2 = *(const float4*)(accrow + c);
        #pragma unroll
        for (int e = 0; e < 4; e++) {
            float hv = (e==0)?h2.x:(e==1)?h2.y:(e==2)?h2.z:h2.w;
            const float4* w4 = (const float4*)(wout_s + (half*128 + c + e)*NHo);
            float4 w0 = w4[0], w1 = w4[1];
            s[0] = fmaf(hv, w0.x, s[0]); s[1] = fmaf(hv, w0.y, s[1]);
            s[2] = fmaf(hv, w0.z, s[2]); s[3] = fmaf(hv, w0.w, s[3]);
            s[4] = fmaf(hv, w1.x, s[4]); s[5] = fmaf(hv, w1.y, s[5]);
            s[6] = fmaf(hv, w1.z, s[6]); s[7] = fmaf(hv, w1.w, s[7]);
        }
    }
    if (half == 1) {
        *(float4*)(red + row3*8)     = make_float4(s[0], s[1], s[2], s[3]);
        *(float4*)(red + row3*8 + 4) = make_float4(s[4], s[5], s[6], s[7]);
    }
    __syncthreads();
    if (half == 0) {
        const int b = row3 & 7;
        const int j = j0 + (row3 >> 3);
        bool m = (mask[b*Ln + i] != 0) && (mask[b*Ln + j] != 0);
        #pragma unroll
        for (int o = 0; o < 8; o++) {
            float v = s[o] + red[row3*8 + o] + b_out[o];
            if (!m) v = -CUDART_INF_F;
            out[((size_t)(b*NHo + o))*(Ln*Ln) + (size_t)i*Ln + j] = v;
        }
    }
}

// ---------------------------------------------------------------------------
extern "C" void kernel_launch(void* const* d_in, const int* in_sizes, int n_in,
                              void* d_out, int out_size) {
    const float* x     = (const float*)d_in[0];
    const float* dist  = (const float*)d_in[1];
    const int*   mask  = (const int*)d_in[2];
    const float* W_rbf = (const float*)d_in[3];
    const float* b_rbf = (const float*)d_in[4];
    const float* W1    = (const float*)d_in[5];
    const float* W2    = (const float*)d_in[6];
    const float* W3    = (const float*)d_in[7];
    const float* b_in  = (const float*)d_in[8];
    const float* W_res = (const float*)d_in[9];
    const float* b_res = (const float*)d_in[10];
    const float* W_out = (const float*)d_in[11];
    const float* b_out = (const float*)d_in[12];
    float*       out   = (float*)d_out;

    prep_kernel<<<PR_TOT, 256>>>(x, W_rbf, b_rbf, W1, W2, W3, b_in, W_res);

    cudaFuncSetAttribute(pair_kernel, cudaFuncAttributeMaxDynamicSharedMemorySize, SM_TOTAL);
    dim3 grid(Ln / TJ, Ln);
    pair_kernel<<<grid, 256, SM_TOTAL>>>(dist, mask, b_res, W_out, b_out, out);
}

// round 6
// speedup vs baseline: 4.6144x; 1.1456x over previous
#include <cuda_runtime.h>
#include <cuda_fp16.h>
#include <math_constants.h>
#include <cstdint>

#define Ln  128
#define Bb  8
#define Dd  256
#define Hh  256
#define NHo 8
#define NGg 50
#define TJ  16
#define ROWS 128

// strides
#define H1_STRB  528      // h1/h2 fp16 row stride bytes (264 halves)
#define WT_STRB  528      // WresT fp16 row stride bytes
#define GA_STRB  144      // gauss/WGT fp16 row stride bytes
#define AB_STRF  260      // AB fp32 row stride (floats)
#define WO3_STRB 544      // woutT fp16 row stride bytes

// smem byte offsets
#define SM_H1    0                      // 128*528 = 67584
#define SM_WT    67584                  // 256*528 = 135168 (aliases GA/WGT/AB)
#define SM_GA    (SM_WT)                // 128*144 = 18432
#define SM_WGT   (SM_WT + 18432)        // 256*144 = 36864
#define SM_AB    (SM_WT)                // 128*260*4 = 133120 (fits in 135168)
#define SM_WO3   202752                 // 8*544 = 4352
#define SM_BRES  207104                 // 1024
#define SM_DSM   208128                 // 512
#define SM_TOTAL 208640

// prep row decode boundaries
#define PR_A    (Ln*Bb)                 // 1024
#define PR_BV   (2*Ln*Bb)               // 2048
#define PR_WGT  (2*Ln*Bb + NGg)         // 2098
#define PR_CV   (2*Ln*Bb + NGg + 1)     // 2099
#define PR_TOT  (PR_CV + Hh)            // 2355

// ---- device scratch (no allocs allowed) ----
__device__ float  g_A[Ln*Bb*Hh];      // x @ W1, row j*8+b
__device__ float  g_Bv[Ln*Bb*Hh];     // x @ W2, row i*8+b
__device__ float  g_cvec[Hh];         // b_in + b_rbf @ W3
__device__ __half g_WGT[Hh*64];       // [h][g] = (W_rbf@W3)[g][h], g>=50 zero
__device__ __half g_WresT[Hh*Hh];     // [n][k] = W_res[k][n]

__device__ __forceinline__ float gelu_f(float x) {
    float u = 0.7978845608028654f * fmaf(0.044715f * x, x * x, x);
    float t;
    asm("tanh.approx.f32 %0, %1;" : "=f"(t) : "f"(u));
    return 0.5f * x * (1.0f + t);
}

__device__ __forceinline__ void mma16816(float* c, const uint32_t* a, const uint32_t* b) {
    asm volatile(
        "mma.sync.aligned.m16n8k16.row.col.f32.f16.f16.f32 "
        "{%0,%1,%2,%3}, {%4,%5,%6,%7}, {%8,%9}, {%0,%1,%2,%3};"
        : "+f"(c[0]), "+f"(c[1]), "+f"(c[2]), "+f"(c[3])
        : "r"(a[0]), "r"(a[1]), "r"(a[2]), "r"(a[3]), "r"(b[0]), "r"(b[1]));
}

// Warp GEMM block: acc[4][8] m16n8k16 frags; A row-major [m][k] fp16, B [n][k] fp16.
// c0=(r,c) c1=(r,c+1) c2=(r+8,c) c3=(r+8,c+1), r=mrow0+mt*16+g, c=ncol0+nt*8+tg*2.
template<int KS>
__device__ __forceinline__ void mma_block(
    const uint8_t* Abase, int astr_b, const uint8_t* Bbase, int bstr_b,
    int mrow0, int ncol0, int g, int tg, float acc[4][8][4])
{
    #pragma unroll
    for (int ks = 0; ks < KS; ks++) {
        const int k0 = ks * 16;
        uint32_t bf[8][2];
        #pragma unroll
        for (int nt = 0; nt < 8; nt++) {
            const uint8_t* bp = Bbase + (ncol0 + nt*8 + g) * bstr_b + (k0 + tg*2) * 2;
            bf[nt][0] = *(const uint32_t*)bp;
            bf[nt][1] = *(const uint32_t*)(bp + 16);
        }
        uint32_t af[4][4];
        #pragma unroll
        for (int mt = 0; mt < 4; mt++) {
            const uint8_t* ap = Abase + (mrow0 + mt*16 + g) * astr_b + (k0 + tg*2) * 2;
            af[mt][0] = *(const uint32_t*)ap;
            af[mt][1] = *(const uint32_t*)(ap + 8*astr_b);
            af[mt][2] = *(const uint32_t*)(ap + 16);
            af[mt][3] = *(const uint32_t*)(ap + 8*astr_b + 16);
        }
        #pragma unroll
        for (int mt = 0; mt < 4; mt++)
            #pragma unroll
            for (int nt = 0; nt < 8; nt++)
                mma16816(acc[mt][nt], af[mt], bf[nt]);
    }
}

// ======================= prep =======================
__global__ void __launch_bounds__(256) prep_kernel(
    const float* __restrict__ x,     const float* __restrict__ W_rbf,
    const float* __restrict__ b_rbf, const float* __restrict__ W1,
    const float* __restrict__ W2,    const float* __restrict__ W3,
    const float* __restrict__ b_in,  const float* __restrict__ W_res)
{
    const int row = blockIdx.x;
    const int h   = threadIdx.x;

    if (row >= PR_CV) {                // WresT rows: PR_CV .. PR_CV+255
        int k = row - PR_CV;
        g_WresT[h*Hh + k] = __float2half(W_res[k*Hh + h]);
        return;
    }

    __shared__ float vsm[Dd];
    const float* vec; const float* Wm;
    if (row < PR_A)        { vec = x + row*Dd;               Wm = W1; }
    else if (row < PR_BV)  { vec = x + (row - PR_A)*Dd;      Wm = W2; }
    else if (row < PR_WGT) { vec = W_rbf + (row - PR_BV)*Dd; Wm = W3; }
    else                   { vec = b_rbf;                    Wm = W3; }

    vsm[h] = vec[h];
    __syncthreads();

    float acc = 0.0f;
    #pragma unroll 8
    for (int d = 0; d < Dd; d++)
        acc = fmaf(vsm[d], Wm[d*Hh + h], acc);

    if (row < PR_A)        g_A[row*Hh + h] = acc;
    else if (row < PR_BV)  g_Bv[(row - PR_A)*Hh + h] = acc;
    else if (row < PR_WGT) g_WGT[h*64 + (row - PR_BV)] = __float2half(acc);
    else {
        g_cvec[h] = acc + b_in[h];
        #pragma unroll
        for (int g = NGg; g < 64; g++) g_WGT[h*64 + g] = __float2half(0.0f);
    }
}

// ======================= main fused HMMA kernel =======================
__global__ void __launch_bounds__(256, 1) pair_kernel(
    const float* __restrict__ dist, const int* __restrict__ mask,
    const float* __restrict__ b_res, const float* __restrict__ W_out,
    const float* __restrict__ b_out, float* __restrict__ out)
{
    extern __shared__ __align__(16) uint8_t smem[];

    const int t    = threadIdx.x;
    const int wid  = t >> 5;
    const int lane = t & 31;
    const int g    = lane >> 2;
    const int tg   = lane & 3;
    const int i    = blockIdx.y;
    const int j0   = blockIdx.x * TJ;
    const int mrow0 = (wid & 1) * 64;
    const int ncol0 = (wid >> 1) * 64;

    float* bres_s = (float*)(smem + SM_BRES);
    float* dsm    = (float*)(smem + SM_DSM);

    // ---- stage small buffers + WGT + woutT(fp16) ----
    bres_s[t] = b_res[t];
    if (t < ROWS) dsm[t] = dist[i*(Ln*Bb) + j0*Bb + t];
    {
        // woutT[o][k] fp16 <- W_out[k][o]
        float4 w0 = *(const float4*)(W_out + t*NHo);
        float4 w1 = *(const float4*)(W_out + t*NHo + 4);
        __half* wo = (__half*)(smem + SM_WO3);
        wo[0*272 + t] = __float2half(w0.x);
        wo[1*272 + t] = __float2half(w0.y);
        wo[2*272 + t] = __float2half(w0.z);
        wo[3*272 + t] = __float2half(w0.w);
        wo[4*272 + t] = __float2half(w1.x);
        wo[5*272 + t] = __float2half(w1.y);
        wo[6*272 + t] = __float2half(w1.z);
        wo[7*272 + t] = __float2half(w1.w);
    }
    {
        const uint4* wgt4 = (const uint4*)g_WGT;   // 256 rows x 8 uint4
        #pragma unroll
        for (int q = 0; q < 8; q++) {
            int u = t + q*256;
            int n = u >> 3, c = u & 7;
            *(uint4*)(smem + SM_WGT + n*GA_STRB + c*16) = wgt4[u];
        }
    }
    __syncthreads();

    // ---- gaussian smearing -> GA fp16 [128][64], zero-padded k>=50 ----
    {
        const float delta = 12.0f / 49.0f;
        const float coeff = -0.5f / (delta * delta);
        #pragma unroll
        for (int q = 0; q < 16; q++) {
            int p2 = t + 256*q;            // half2 index
            int r = p2 >> 5, kp = p2 & 31;
            int k = 2*kp;
            float d = dsm[r];
            float v0 = 0.0f, v1 = 0.0f;
            if (k < NGg)     { float d0 = d - delta*(float)k;     v0 = __expf(coeff*d0*d0); }
            if (k+1 < NGg)   { float d1 = d - delta*(float)(k+1); v1 = __expf(coeff*d1*d1); }
            *(__half2*)(smem + SM_GA + r*GA_STRB + k*2) = __floats2half2_rn(v0, v1);
        }
    }
    __syncthreads();

    float acc[4][8][4];
    #pragma unroll
    for (int mt = 0; mt < 4; mt++)
        #pragma unroll
        for (int nt = 0; nt < 8; nt++)
            #pragma unroll
            for (int e = 0; e < 4; e++) acc[mt][nt][e] = 0.0f;

    // ---- MMA1: D1 = gauss[128x64] @ WG[64x256]  (acc stays in regs) ----
    mma_block<4>(smem + SM_GA, GA_STRB, smem + SM_WGT, GA_STRB, mrow0, ncol0, g, tg, acc);
    __syncthreads();                       // all warps done reading GA/WGT

    // ---- stage AB = g_A(j-row) + g_Bv(i,b) + cvec (overwrites GA/WGT) ----
    #pragma unroll
    for (int q = 0; q < 32; q++) {
        int e4 = t + 256*q;                // float4 index over [128][64]
        int row = e4 >> 6;
        int col = (e4 & 63) * 4;
        float4 xa = *(const float4*)(g_A  + (size_t)(j0*Bb + row)*Hh + col);
        float4 xb = *(const float4*)(g_Bv + (size_t)(i*Bb + (row & 7))*Hh + col);
        float4 cv = *(const float4*)(g_cvec + col);
        float4 o;
        o.x = xa.x + xb.x + cv.x;
        o.y = xa.y + xb.y + cv.y;
        o.z = xa.z + xb.z + cv.z;
        o.w = xa.w + xb.w + cv.w;
        *(float4*)(smem + SM_AB + (size_t)(row*AB_STRF + col)*4) = o;
    }
    __syncthreads();

    // ---- epilogue 1 (fragment layout): h1 = gelu(D1 + AB) -> fp16 ----
    #pragma unroll
    for (int mt = 0; mt < 4; mt++) {
        const int r = mrow0 + mt*16 + g;
        #pragma unroll
        for (int nt = 0; nt < 8; nt++) {
            const int c = ncol0 + nt*8 + tg*2;
            float2 ab0 = *(const float2*)(smem + SM_AB + (size_t)(r*AB_STRF + c)*4);
            float2 ab1 = *(const float2*)(smem + SM_AB + (size_t)((r+8)*AB_STRF + c)*4);
            __half2 h0 = __floats2half2_rn(gelu_f(acc[mt][nt][0] + ab0.x),
                                           gelu_f(acc[mt][nt][1] + ab0.y));
            __half2 h1 = __floats2half2_rn(gelu_f(acc[mt][nt][2] + ab1.x),
                                           gelu_f(acc[mt][nt][3] + ab1.y));
            *(__half2*)(smem + SM_H1 + r*H1_STRB + c*2)     = h0;
            *(__half2*)(smem + SM_H1 + (r+8)*H1_STRB + c*2) = h1;
        }
    }
    __syncthreads();                       // AB reads done; h1 complete

    // ---- stage WresT [256][256] fp16 (overwrites AB) ----
    {
        const uint4* ws4 = (const uint4*)g_WresT;  // 256 rows x 32 uint4
        #pragma unroll
        for (int q = 0; q < 32; q++) {
            int u = t + 256*q;
            int n = u >> 5, c = u & 31;
            *(uint4*)(smem + SM_WT + n*WT_STRB + c*16) = ws4[u];
        }
    }
    __syncthreads();

    // ---- MMA2: D2 = h1[128x256] @ W_res[256x256] ----
    #pragma unroll
    for (int mt = 0; mt < 4; mt++)
        #pragma unroll
        for (int nt = 0; nt < 8; nt++)
            #pragma unroll
            for (int e = 0; e < 4; e++) acc[mt][nt][e] = 0.0f;
    mma_block<16>(smem + SM_H1, H1_STRB, smem + SM_WT, WT_STRB, mrow0, ncol0, g, tg, acc);
    __syncthreads();                       // all warps done reading h1/WT

    // ---- epilogue 2 (fragment, in place): h2 = h1 + gelu(D2 + b_res) -> fp16 ----
    #pragma unroll
    for (int mt = 0; mt < 4; mt++) {
        const int r = mrow0 + mt*16 + g;
        #pragma unroll
        for (int nt = 0; nt < 8; nt++) {
            const int c = ncol0 + nt*8 + tg*2;
            float2 br = *(const float2*)(bres_s + c);
            __half2* p0 = (__half2*)(smem + SM_H1 + r*H1_STRB + c*2);
            __half2* p1 = (__half2*)(smem + SM_H1 + (r+8)*H1_STRB + c*2);
            float2 f0 = __half22float2(*p0);
            float2 f1 = __half22float2(*p1);
            float n00 = f0.x + gelu_f(acc[mt][nt][0] + br.x);
            float n01 = f0.y + gelu_f(acc[mt][nt][1] + br.y);
            float n10 = f1.x + gelu_f(acc[mt][nt][2] + br.x);
            float n11 = f1.y + gelu_f(acc[mt][nt][3] + br.y);
            *p0 = __floats2half2_rn(n00, n01);
            *p1 = __floats2half2_rn(n10, n11);
        }
    }
    __syncthreads();                       // h2 complete for cross-warp reads

    // ---- phase 3 (HMMA): out[128x8] = h2[128x256] @ woutT^T ----
    {
        float a3[4] = {0.0f, 0.0f, 0.0f, 0.0f};
        const int r3 = wid * 16;           // warp owns rows r3..r3+15
        #pragma unroll
        for (int ks = 0; ks < 16; ks++) {
            const int k0 = ks * 16;
            uint32_t af[4];
            const uint8_t* ap = smem + SM_H1 + (r3 + g)*H1_STRB + (k0 + tg*2)*2;
            af[0] = *(const uint32_t*)ap;
            af[1] = *(const uint32_t*)(ap + 8*H1_STRB);
            af[2] = *(const uint32_t*)(ap + 16);
            af[3] = *(const uint32_t*)(ap + 8*H1_STRB + 16);
            uint32_t bf[2];
            const uint8_t* bp = smem + SM_WO3 + g*WO3_STRB + (k0 + tg*2)*2;
            bf[0] = *(const uint32_t*)bp;
            bf[1] = *(const uint32_t*)(bp + 16);
            mma16816(a3, af, bf);
        }
        // a3: c0=(r3+g, 2tg) c1=(r3+g, 2tg+1) c2=(r3+g+8, 2tg) c3=(r3+g+8, 2tg+1)
        float2 bo = *(const float2*)(b_out + tg*2);
        #pragma unroll
        for (int h = 0; h < 2; h++) {
            const int r = r3 + g + h*8;
            const int b = r & 7;
            const int j = j0 + (r >> 3);
            bool m = (mask[b*Ln + i] != 0) && (mask[b*Ln + j] != 0);
            float v0 = a3[2*h + 0] + bo.x;
            float v1 = a3[2*h + 1] + bo.y;
            if (!m) { v0 = -CUDART_INF_F; v1 = -CUDART_INF_F; }
            size_t base = ((size_t)(b*NHo + tg*2))*(Ln*Ln) + (size_t)i*Ln + j;
            out[base]         = v0;
            out[base + Ln*Ln] = v1;
        }
    }
}

// ---------------------------------------------------------------------------
extern "C" void kernel_launch(void* const* d_in, const int* in_sizes, int n_in,
                              void* d_out, int out_size) {
    const float* x     = (const float*)d_in[0];
    const float* dist  = (const float*)d_in[1];
    const int*   mask  = (const int*)d_in[2];
    const float* W_rbf = (const float*)d_in[3];
    const float* b_rbf = (const float*)d_in[4];
    const float* W1    = (const float*)d_in[5];
    const float* W2    = (const float*)d_in[6];
    const float* W3    = (const float*)d_in[7];
    const float* b_in  = (const float*)d_in[8];
    const float* W_res = (const float*)d_in[9];
    const float* b_res = (const float*)d_in[10];
    const float* W_out = (const float*)d_in[11];
    const float* b_out = (const float*)d_in[12];
    float*       out   = (float*)d_out;

    prep_kernel<<<PR_TOT, 256>>>(x, W_rbf, b_rbf, W1, W2, W3, b_in, W_res);

    cudaFuncSetAttribute(pair_kernel, cudaFuncAttributeMaxDynamicSharedMemorySize, SM_TOTAL);
    dim3 grid(Ln / TJ, Ln);
    pair_kernel<<<grid, 256, SM_TOTAL>>>(dist, mask, b_res, W_out, b_out, out);
}